// round 12
// baseline (speedup 1.0000x reference)
#include <cuda_runtime.h>
#include <cuda_bf16.h>
#include <mma.h>
#include <cstdint>

using namespace nvcuda;

#define NN 512
#define BB 64
#define FF 128

#define BM 128
#define BK 32
#define ALDM 40    // As row stride in bf16 (80B rows, 16B-aligned)
#define BLDM 136   // Bs row stride in bf16 (272B rows)
#define ELD  68    // epilogue fp32 buffer row stride
#define NKT (NN / BK)

#define NSTAGE 4
#define STAGE_ELEMS (BM * ALDM + BK * BLDM)        // 9472 bf16
#define STAGE_BYTES (STAGE_ELEMS * 2)              // 18944 B
#define SMEM_BYTES  (NSTAGE * STAGE_BYTES)         // 75776 B (>= 34816 epi buf)

// scratch (allocations forbidden -> device globals)
__device__ float g_smw[NN * NN];               // softmax(weight), fp32
__device__ float g_d[BB * NN];                 // rsqrt degree
__device__ __nv_bfloat16 g_xd[BB * NN * FF];   // bf16(d_k * x[b,k,f])
__device__ __nv_bfloat16 g_A[(size_t)BB * NN * NN];  // bf16(sm[i,k]*mask[b,i,k])

__device__ __forceinline__ unsigned int bf2_as_u32(__nv_bfloat162 v) {
    unsigned int r;
    memcpy(&r, &v, 4);
    return r;
}
__device__ __forceinline__ uint32_t smem_u32(const void* p) {
    uint32_t a;
    asm("{ .reg .u64 t; cvta.to.shared.u64 t, %1; cvt.u32.u64 %0, t; }" : "=r"(a) : "l"(p));
    return a;
}
__device__ __forceinline__ void cp_async16(uint32_t dst, const void* src) {
    asm volatile("cp.async.cg.shared.global [%0], [%1], 16;" :: "r"(dst), "l"(src));
}
#define CP_COMMIT() asm volatile("cp.async.commit_group;" ::: "memory")
#define CP_WAIT(n)  asm volatile("cp.async.wait_group %0;" :: "n"(n) : "memory")

// ---------------------------------------------------------------------------
// Kernel 1: row softmax of weight [512,512]. Warp per row.
// ---------------------------------------------------------------------------
__global__ __launch_bounds__(128) void softmax_kernel(const float* __restrict__ w) {
    int warp = threadIdx.x >> 5;
    int lane = threadIdx.x & 31;
    int row  = blockIdx.x * 4 + warp;

    const float4* wr = (const float4*)(w + (size_t)row * NN);
    float4 v[4];
    float mx = -1e30f;
#pragma unroll
    for (int j = 0; j < 4; j++) {
        v[j] = wr[lane + 32 * j];
        mx = fmaxf(mx, fmaxf(fmaxf(v[j].x, v[j].y), fmaxf(v[j].z, v[j].w)));
    }
#pragma unroll
    for (int o = 16; o; o >>= 1) mx = fmaxf(mx, __shfl_xor_sync(0xffffffffu, mx, o));

    float s = 0.0f;
#pragma unroll
    for (int j = 0; j < 4; j++) {
        v[j].x = __expf(v[j].x - mx);
        v[j].y = __expf(v[j].y - mx);
        v[j].z = __expf(v[j].z - mx);
        v[j].w = __expf(v[j].w - mx);
        s += v[j].x + v[j].y + v[j].z + v[j].w;
    }
#pragma unroll
    for (int o = 16; o; o >>= 1) s += __shfl_xor_sync(0xffffffffu, s, o);
    float inv = 1.0f / s;

    float4* orow = (float4*)(g_smw + (size_t)row * NN);
#pragma unroll
    for (int j = 0; j < 4; j++) {
        v[j].x *= inv; v[j].y *= inv; v[j].z *= inv; v[j].w *= inv;
        orow[lane + 32 * j] = v[j];
    }
}

// ---------------------------------------------------------------------------
// Kernel 2: per (b,i): prod = sm[i,:]*mask[b,i,:]; g_A = bf16(prod);
// d = rsqrt(1 + sum(prod)) (>0 guard); g_d = d; g_xd[b,i,:] = bf16(d*x[b,i,:]).
// Warp per row, 8 rows per block. grid (64, 64) x 256.
// ---------------------------------------------------------------------------
__global__ __launch_bounds__(256) void degree_xd_kernel(
    const float* __restrict__ mask, const float* __restrict__ x) {
    int warp = threadIdx.x >> 5;
    int lane = threadIdx.x & 31;
    int i = blockIdx.x * 8 + warp;
    int b = blockIdx.y;

    const float4* mr = (const float4*)(mask + ((size_t)b * NN + i) * NN);
    const float4* sr = (const float4*)(g_smw + (size_t)i * NN);
    uint2* ar = (uint2*)(g_A + ((size_t)b * NN + i) * NN);
    float s = 0.0f;
#pragma unroll
    for (int j = 0; j < 4; j++) {
        float4 m4 = mr[lane + 32 * j];
        float4 s4 = sr[lane + 32 * j];
        float4 p = make_float4(m4.x * s4.x, m4.y * s4.y, m4.z * s4.z, m4.w * s4.w);
        s += p.x + p.y + p.z + p.w;
        uint2 pk;
        pk.x = bf2_as_u32(__float22bfloat162_rn(make_float2(p.x, p.y)));
        pk.y = bf2_as_u32(__float22bfloat162_rn(make_float2(p.z, p.w)));
        ar[lane + 32 * j] = pk;
    }
#pragma unroll
    for (int o = 16; o > 0; o >>= 1) s += __shfl_xor_sync(0xffffffffu, s, o);
    float tot = s + 1.0f;  // +1 from identity
    float d = (tot > 0.0f) ? rsqrtf(tot) : 0.0f;
    if (lane == 0) g_d[b * NN + i] = d;

    float4 xv = *(const float4*)(x + ((size_t)b * NN + i) * FF + lane * 4);
    uint2 pk;
    pk.x = bf2_as_u32(__float22bfloat162_rn(make_float2(xv.x * d, xv.y * d)));
    pk.y = bf2_as_u32(__float22bfloat162_rn(make_float2(xv.z * d, xv.w * d)));
    *(uint2*)(g_xd + ((size_t)b * NN + i) * FF + lane * 4) = pk;
}

// ---------------------------------------------------------------------------
// Kernel 3: bf16 wmma GEMM, 4-stage cp.async pipeline (pure copies).
// out[b,i,f] = d_i * sum_k A'[b,i,k] * xd[b,k,f] + d_i^2 * x[b,i,f]
// ---------------------------------------------------------------------------
__global__ __launch_bounds__(256, 2) void gcn_gemm_wmma(
    const float* __restrict__ x,     // [B,N,F]
    float* __restrict__ out)         // [B,N,F]
{
    extern __shared__ __align__(128) char smem[];

    const int b  = blockIdx.y;
    const int i0 = blockIdx.x * BM;
    const int t  = threadIdx.x;
    const int warp = t >> 5;
    const int wm = (warp & 3) * 32;   // warp m offset
    const int wn = (warp >> 2) * 64;  // warp n offset

    const float* xB = x + (size_t)b * NN * FF;
    const __nv_bfloat16* AB  = g_A + ((size_t)b * NN + i0) * NN;
    const __nv_bfloat16* xdB = g_xd + (size_t)b * NN * FF;
    const float* dB = g_d + b * NN;

    // A loader: row a_i (+64 on pass 1), 8 bf16 (16B) at a_k
    const int a_i = t >> 2;          // 0..63
    const int a_k = (t & 3) * 8;
    // B loader: row b_k (0..31), 16 bf16 (32B) at b_f
    const int b_k = t >> 3;
    const int b_f = (t & 7) * 16;

    wmma::fragment<wmma::accumulator, 16, 16, 16, float> acc[2][4];
#pragma unroll
    for (int im = 0; im < 2; im++)
#pragma unroll
        for (int jn = 0; jn < 4; jn++) wmma::fill_fragment(acc[im][jn], 0.0f);

    const uint32_t smem_base = smem_u32(smem);

    // issue cp.asyncs for tile kt into stage s
    auto issue_tile = [&](int kt, int s) {
        const int k0 = kt * BK;
        uint32_t As_u = smem_base + (uint32_t)(s * STAGE_BYTES);
        uint32_t Bs_u = As_u + BM * ALDM * 2;
#pragma unroll
        for (int p = 0; p < 2; p++) {
            int i = a_i + p * 64;
            cp_async16(As_u + (i * ALDM + a_k) * 2, AB + (size_t)i * NN + k0 + a_k);
        }
        cp_async16(Bs_u + (b_k * BLDM + b_f) * 2,     xdB + (size_t)(k0 + b_k) * FF + b_f);
        cp_async16(Bs_u + (b_k * BLDM + b_f + 8) * 2, xdB + (size_t)(k0 + b_k) * FF + b_f + 8);
        CP_COMMIT();
    };

    issue_tile(0, 0);
    issue_tile(1, 1);
    issue_tile(2, 2);

    for (int kt = 0; kt < NKT; ++kt) {
        // ensure tile kt complete (tail-exact wait depth)
        if (kt + 2 < NKT)      CP_WAIT(2);
        else if (kt + 1 < NKT) CP_WAIT(1);
        else                   CP_WAIT(0);
        __syncthreads();   // tile kt visible to all; also orders stage reuse below

        if (kt + 3 < NKT) issue_tile(kt + 3, (kt + 3) & 3);  // overlaps MMA below

        const __nv_bfloat16* As =
            (const __nv_bfloat16*)(smem + (kt & 3) * STAGE_BYTES);
        const __nv_bfloat16* Bs = As + BM * ALDM;

#pragma unroll
        for (int kk = 0; kk < 2; kk++) {
            wmma::fragment<wmma::matrix_a, 16, 16, 16, __nv_bfloat16, wmma::row_major> af[2];
            wmma::fragment<wmma::matrix_b, 16, 16, 16, __nv_bfloat16, wmma::row_major> bf[4];
#pragma unroll
            for (int im = 0; im < 2; im++)
                wmma::load_matrix_sync(af[im], As + (wm + im * 16) * ALDM + kk * 16, ALDM);
#pragma unroll
            for (int jn = 0; jn < 4; jn++)
                wmma::load_matrix_sync(bf[jn], Bs + (kk * 16) * BLDM + wn + jn * 16, BLDM);
#pragma unroll
            for (int im = 0; im < 2; im++)
#pragma unroll
                for (int jn = 0; jn < 4; jn++)
                    wmma::mma_sync(acc[im][jn], af[im], bf[jn], acc[im][jn]);
        }
    }

    // ---- epilogue: stage acc through smem (two n-halves), apply
    //      out = d_i * acc + d_i^2 * x[i,f] in fp32
    float* buf = (float*)smem;  // [BM][ELD] = 34816 B, reuses stages 0-1
    const int er = t >> 1;             // row 0..127
    const int ec = (t & 1) * 32;       // col half within 64
#pragma unroll
    for (int half = 0; half < 2; half++) {
        __syncthreads();
        if ((warp >> 2) == half) {
#pragma unroll
            for (int im = 0; im < 2; im++)
#pragma unroll
                for (int jn = 0; jn < 4; jn++)
                    wmma::store_matrix_sync(buf + (wm + im * 16) * ELD + jn * 16,
                                            acc[im][jn], ELD, wmma::mem_row_major);
        }
        __syncthreads();

        int gi = i0 + er;
        float di  = dB[gi];
        float di2 = di * di;
        const float* xr = xB + (size_t)gi * FF + half * 64 + ec;
        float* orow     = out + ((size_t)b * NN + gi) * FF + half * 64 + ec;
#pragma unroll
        for (int q = 0; q < 8; q++) {
            float4 v  = *(const float4*)(buf + er * ELD + ec + q * 4);
            float4 xv = *(const float4*)(xr + q * 4);
            float4 o;
            o.x = di * v.x + di2 * xv.x;
            o.y = di * v.y + di2 * xv.y;
            o.z = di * v.z + di2 * xv.z;
            o.w = di * v.w + di2 * xv.w;
            *(float4*)(orow + q * 4) = o;
        }
    }
}

// ---------------------------------------------------------------------------
extern "C" void kernel_launch(void* const* d_in, const int* in_sizes, int n_in,
                              void* d_out, int out_size) {
    const float* input  = nullptr;  // 64*512*128
    const float* mask   = nullptr;  // 64*512*512
    const float* weight = nullptr;  // 512*512
    for (int i = 0; i < n_in; i++) {
        if (in_sizes[i] == BB * NN * FF)      input  = (const float*)d_in[i];
        else if (in_sizes[i] == BB * NN * NN) mask   = (const float*)d_in[i];
        else if (in_sizes[i] == NN * NN)      weight = (const float*)d_in[i];
    }
    float* out = (float*)d_out;

    cudaFuncSetAttribute(gcn_gemm_wmma,
                         cudaFuncAttributeMaxDynamicSharedMemorySize, SMEM_BYTES);

    softmax_kernel<<<128, 128>>>(weight);
    degree_xd_kernel<<<dim3(64, BB), 256>>>(mask, input);
    gcn_gemm_wmma<<<dim3(NN / BM, BB), 256, SMEM_BYTES>>>(input, out);
}

// round 13
// speedup vs baseline: 1.0258x; 1.0258x over previous
#include <cuda_runtime.h>
#include <cuda_bf16.h>
#include <mma.h>
#include <cstdint>

using namespace nvcuda;

#define NN 512
#define BB 64
#define FF 128

#define BM 128
#define BK 64
#define ALDM 72    // As row stride in bf16 (144B rows; ldmatrix conflict-free)
#define BLDM 136   // Bs row stride in bf16 (272B rows)
#define ELD  68    // epilogue fp32 buffer row stride
#define NKT (NN / BK)                              // 8

#define STAGE_ELEMS (BM * ALDM + BK * BLDM)        // 17920 bf16
#define STAGE_BYTES (STAGE_ELEMS * 2)              // 35840 B
#define SMEM_BYTES  (2 * STAGE_BYTES)              // 71680 B (>= 34816 epi buf)

// scratch (allocations forbidden -> device globals)
__device__ float g_d[BB * NN];                 // rsqrt degree
__device__ __nv_bfloat16 g_xd[BB * NN * FF];   // bf16(d_k * x[b,k,f])
__device__ __nv_bfloat16 g_A[(size_t)BB * NN * NN];  // bf16(sm[i,k]*mask[b,i,k])

__device__ __forceinline__ unsigned int bf2_as_u32(__nv_bfloat162 v) {
    unsigned int r;
    memcpy(&r, &v, 4);
    return r;
}
__device__ __forceinline__ uint32_t smem_u32(const void* p) {
    uint32_t a;
    asm("{ .reg .u64 t; cvta.to.shared.u64 t, %1; cvt.u32.u64 %0, t; }" : "=r"(a) : "l"(p));
    return a;
}
__device__ __forceinline__ void cp_async16(uint32_t dst, const void* src) {
    asm volatile("cp.async.cg.shared.global [%0], [%1], 16;" :: "r"(dst), "l"(src));
}
#define CP_COMMIT() asm volatile("cp.async.commit_group;" ::: "memory")
#define CP_WAIT(n)  asm volatile("cp.async.wait_group %0;" :: "n"(n) : "memory")

// ---------------------------------------------------------------------------
// Kernel 1 (fused prep): per (b,i) row, one warp:
//   softmax of weight row i (recomputed per b; bitwise-identical to the old
//   separate kernel), prod = sm*mask, g_A = bf16(prod),
//   d = rsqrt(1 + sum(prod)) (>0 guard), g_d = d, g_xd = bf16(d*x).
// grid (64, 64) x 256 (8 warps = 8 rows/block).
// ---------------------------------------------------------------------------
__global__ __launch_bounds__(256) void prep_kernel(
    const float* __restrict__ w, const float* __restrict__ mask,
    const float* __restrict__ x) {
    int warp = threadIdx.x >> 5;
    int lane = threadIdx.x & 31;
    int i = blockIdx.x * 8 + warp;
    int b = blockIdx.y;

    // ---- softmax of weight row i (in registers; w row is L2-hot)
    const float4* wr = (const float4*)(w + (size_t)i * NN);
    float4 v[4];
    float mx = -1e30f;
#pragma unroll
    for (int j = 0; j < 4; j++) {
        v[j] = wr[lane + 32 * j];
        mx = fmaxf(mx, fmaxf(fmaxf(v[j].x, v[j].y), fmaxf(v[j].z, v[j].w)));
    }
#pragma unroll
    for (int o = 16; o; o >>= 1) mx = fmaxf(mx, __shfl_xor_sync(0xffffffffu, mx, o));
    float s0 = 0.0f;
#pragma unroll
    for (int j = 0; j < 4; j++) {
        v[j].x = __expf(v[j].x - mx);
        v[j].y = __expf(v[j].y - mx);
        v[j].z = __expf(v[j].z - mx);
        v[j].w = __expf(v[j].w - mx);
        s0 += v[j].x + v[j].y + v[j].z + v[j].w;
    }
#pragma unroll
    for (int o = 16; o; o >>= 1) s0 += __shfl_xor_sync(0xffffffffu, s0, o);
    float inv = 1.0f / s0;
#pragma unroll
    for (int j = 0; j < 4; j++) {
        v[j].x *= inv; v[j].y *= inv; v[j].z *= inv; v[j].w *= inv;
    }

    // ---- masked product, g_A store, degree sum
    const float4* mr = (const float4*)(mask + ((size_t)b * NN + i) * NN);
    uint2* ar = (uint2*)(g_A + ((size_t)b * NN + i) * NN);
    float s = 0.0f;
#pragma unroll
    for (int j = 0; j < 4; j++) {
        float4 m4 = mr[lane + 32 * j];
        float4 p = make_float4(m4.x * v[j].x, m4.y * v[j].y, m4.z * v[j].z, m4.w * v[j].w);
        s += p.x + p.y + p.z + p.w;
        uint2 pk;
        pk.x = bf2_as_u32(__float22bfloat162_rn(make_float2(p.x, p.y)));
        pk.y = bf2_as_u32(__float22bfloat162_rn(make_float2(p.z, p.w)));
        ar[lane + 32 * j] = pk;
    }
#pragma unroll
    for (int o = 16; o > 0; o >>= 1) s += __shfl_xor_sync(0xffffffffu, s, o);
    float tot = s + 1.0f;  // +1 from identity
    float d = (tot > 0.0f) ? rsqrtf(tot) : 0.0f;
    if (lane == 0) g_d[b * NN + i] = d;

    float4 xv = *(const float4*)(x + ((size_t)b * NN + i) * FF + lane * 4);
    uint2 pk;
    pk.x = bf2_as_u32(__float22bfloat162_rn(make_float2(xv.x * d, xv.y * d)));
    pk.y = bf2_as_u32(__float22bfloat162_rn(make_float2(xv.z * d, xv.w * d)));
    *(uint2*)(g_xd + ((size_t)b * NN + i) * FF + lane * 4) = pk;
}

// ---------------------------------------------------------------------------
// Kernel 2: bf16 wmma GEMM, BK=64, 2-stage cp.async pipeline (pure copies).
// out[b,i,f] = d_i * sum_k A'[b,i,k] * xd[b,k,f] + d_i^2 * x[b,i,f]
// ---------------------------------------------------------------------------
__global__ __launch_bounds__(256, 2) void gcn_gemm_wmma(
    const float* __restrict__ x,     // [B,N,F]
    float* __restrict__ out)         // [B,N,F]
{
    extern __shared__ __align__(128) char smem[];

    const int b  = blockIdx.y;
    const int i0 = blockIdx.x * BM;
    const int t  = threadIdx.x;
    const int warp = t >> 5;
    const int wm = (warp & 3) * 32;   // warp m offset
    const int wn = (warp >> 2) * 64;  // warp n offset

    const float* xB = x + (size_t)b * NN * FF;
    const __nv_bfloat16* AB  = g_A + ((size_t)b * NN + i0) * NN;
    const __nv_bfloat16* xdB = g_xd + (size_t)b * NN * FF;
    const float* dB = g_d + b * NN;

    // A loader: row a_i (+64 on pass 1), 32B (2x16B) at a_k
    const int a_i = t >> 2;          // 0..63
    const int a_k = (t & 3) * 16;    // 0,16,32,48
    // B loader: row b_k (0..63), 64B (4x16B) at b_f
    const int b_k = t >> 2;          // 0..63
    const int b_f = (t & 3) * 32;    // 0,32,64,96

    wmma::fragment<wmma::accumulator, 16, 16, 16, float> acc[2][4];
#pragma unroll
    for (int im = 0; im < 2; im++)
#pragma unroll
        for (int jn = 0; jn < 4; jn++) wmma::fill_fragment(acc[im][jn], 0.0f);

    const uint32_t smem_base = smem_u32(smem);

    // issue cp.asyncs for tile kt into stage s
    auto issue_tile = [&](int kt, int s) {
        const int k0 = kt * BK;
        uint32_t As_u = smem_base + (uint32_t)(s * STAGE_BYTES);
        uint32_t Bs_u = As_u + BM * ALDM * 2;
#pragma unroll
        for (int p = 0; p < 2; p++) {
            int i = a_i + p * 64;
            cp_async16(As_u + (i * ALDM + a_k) * 2,     AB + (size_t)i * NN + k0 + a_k);
            cp_async16(As_u + (i * ALDM + a_k + 8) * 2, AB + (size_t)i * NN + k0 + a_k + 8);
        }
#pragma unroll
        for (int q = 0; q < 4; q++)
            cp_async16(Bs_u + (b_k * BLDM + b_f + q * 8) * 2,
                       xdB + (size_t)(k0 + b_k) * FF + b_f + q * 8);
        CP_COMMIT();
    };

    issue_tile(0, 0);

    for (int kt = 0; kt < NKT; ++kt) {
        if (kt + 1 < NKT) CP_WAIT(1);
        else              CP_WAIT(0);
        __syncthreads();   // tile kt visible; also orders stage reuse

        if (kt + 1 < NKT) issue_tile(kt + 1, (kt + 1) & 1);  // overlaps MMA below

        const __nv_bfloat16* As =
            (const __nv_bfloat16*)(smem + (kt & 1) * STAGE_BYTES);
        const __nv_bfloat16* Bs = As + BM * ALDM;

#pragma unroll
        for (int kk = 0; kk < 4; kk++) {
            wmma::fragment<wmma::matrix_a, 16, 16, 16, __nv_bfloat16, wmma::row_major> af[2];
            wmma::fragment<wmma::matrix_b, 16, 16, 16, __nv_bfloat16, wmma::row_major> bf[4];
#pragma unroll
            for (int im = 0; im < 2; im++)
                wmma::load_matrix_sync(af[im], As + (wm + im * 16) * ALDM + kk * 16, ALDM);
#pragma unroll
            for (int jn = 0; jn < 4; jn++)
                wmma::load_matrix_sync(bf[jn], Bs + (kk * 16) * BLDM + wn + jn * 16, BLDM);
#pragma unroll
            for (int im = 0; im < 2; im++)
#pragma unroll
                for (int jn = 0; jn < 4; jn++)
                    wmma::mma_sync(acc[im][jn], af[im], bf[jn], acc[im][jn]);
        }
    }

    // ---- epilogue: stage acc through smem (two n-halves), apply
    //      out = d_i * acc + d_i^2 * x[i,f] in fp32
    float* buf = (float*)smem;  // [BM][ELD] = 34816 B, reuses stage 0
    const int er = t >> 1;             // row 0..127
    const int ec = (t & 1) * 32;       // col half within 64
#pragma unroll
    for (int half = 0; half < 2; half++) {
        __syncthreads();
        if ((warp >> 2) == half) {
#pragma unroll
            for (int im = 0; im < 2; im++)
#pragma unroll
                for (int jn = 0; jn < 4; jn++)
                    wmma::store_matrix_sync(buf + (wm + im * 16) * ELD + jn * 16,
                                            acc[im][jn], ELD, wmma::mem_row_major);
        }
        __syncthreads();

        int gi = i0 + er;
        float di  = dB[gi];
        float di2 = di * di;
        const float* xr = xB + (size_t)gi * FF + half * 64 + ec;
        float* orow     = out + ((size_t)b * NN + gi) * FF + half * 64 + ec;
#pragma unroll
        for (int q = 0; q < 8; q++) {
            float4 v  = *(const float4*)(buf + er * ELD + ec + q * 4);
            float4 xv = *(const float4*)(xr + q * 4);
            float4 o;
            o.x = di * v.x + di2 * xv.x;
            o.y = di * v.y + di2 * xv.y;
            o.z = di * v.z + di2 * xv.z;
            o.w = di * v.w + di2 * xv.w;
            *(float4*)(orow + q * 4) = o;
        }
    }
}

// ---------------------------------------------------------------------------
extern "C" void kernel_launch(void* const* d_in, const int* in_sizes, int n_in,
                              void* d_out, int out_size) {
    const float* input  = nullptr;  // 64*512*128
    const float* mask   = nullptr;  // 64*512*512
    const float* weight = nullptr;  // 512*512
    for (int i = 0; i < n_in; i++) {
        if (in_sizes[i] == BB * NN * FF)      input  = (const float*)d_in[i];
        else if (in_sizes[i] == BB * NN * NN) mask   = (const float*)d_in[i];
        else if (in_sizes[i] == NN * NN)      weight = (const float*)d_in[i];
    }
    float* out = (float*)d_out;

    cudaFuncSetAttribute(gcn_gemm_wmma,
                         cudaFuncAttributeMaxDynamicSharedMemorySize, SMEM_BYTES);

    prep_kernel<<<dim3(64, BB), 256>>>(weight, mask, input);
    gcn_gemm_wmma<<<dim3(NN / BM, BB), 256, SMEM_BYTES>>>(input, out);
}